// round 9
// baseline (speedup 1.0000x reference)
#include <cuda_runtime.h>
#include <cuda_fp16.h>
#include <math.h>
#include <stdint.h>

#define BATCH 32768
#define FDIM 512
#define HS 256
#define OUTD 128
#define STEPS 5
#define EPSBN 1e-5f

typedef __half fp16;

// ---------------- scratch (device globals; no allocation) ----------------
__device__ fp16  g_featsh[BATCH * FDIM];
__device__ fp16  g_A[BATCH * FDIM];
__device__ fp16  g_h0[BATCH * HS];
__device__ fp16  g_h1[BATCH * HS];
__device__ float g_z[BATCH * FDIM];
__device__ float g_prior[BATCH * FDIM];
__device__ float g_acc[BATCH * OUTD];

// prepped weights ([N,K] fp16; GLU ones N-permuted with 8-col a/b interleave)
__device__ fp16 g_W0[512 * 512];
__device__ fp16 g_W1[512 * 256];
__device__ fp16 g_WU[12 * 512 * 256];
__device__ fp16 g_WA[5 * 512 * 128];
__device__ float g_fts[6 * 4 * 512], g_ftt[6 * 4 * 512];
__device__ float g_as[5 * 512], g_at[5 * 512];

// ---------------- PTX helpers ----------------
__device__ __forceinline__ uint32_t smem_u32(const void* p) {
    uint32_t a;
    asm("{ .reg .u64 t; cvta.to.shared.u64 t, %1; cvt.u32.u64 %0, t; }" : "=r"(a) : "l"(p));
    return a;
}
__device__ __forceinline__ void cpa16(uint32_t s, const void* g) {
    asm volatile("cp.async.cg.shared.global [%0], [%1], 16;" :: "r"(s), "l"(g));
}
__device__ __forceinline__ void cpa_commit() {
    asm volatile("cp.async.commit_group;" ::: "memory");
}
template<int N>
__device__ __forceinline__ void cpa_wait() {
    asm volatile("cp.async.wait_group %0;" :: "n"(N) : "memory");
}
__device__ __forceinline__ void ldm4(uint32_t* v, uint32_t addr) {
    asm volatile("ldmatrix.sync.aligned.m8n8.x4.shared.b16 {%0,%1,%2,%3}, [%4];"
                 : "=r"(v[0]), "=r"(v[1]), "=r"(v[2]), "=r"(v[3]) : "r"(addr));
}
__device__ __forceinline__ void mma16(float* c, const uint32_t* a, uint32_t b0, uint32_t b1) {
    asm("mma.sync.aligned.m16n8k16.row.col.f32.f16.f16.f32 "
        "{%0,%1,%2,%3}, {%4,%5,%6,%7}, {%8,%9}, {%0,%1,%2,%3};"
        : "+f"(c[0]), "+f"(c[1]), "+f"(c[2]), "+f"(c[3])
        : "r"(a[0]), "r"(a[1]), "r"(a[2]), "r"(a[3]), "r"(b0), "r"(b1));
}

// ---------------- prep ----------------
__device__ __forceinline__ void prep_one(const float* W, int K, int idx, fp16* o)
{
    int n = idx / K, k = idx - n * K;
    int q = n >> 4, rr = n & 15, half = rr >> 3, jl = rr & 7;
    int col = (half ? 256 : 0) + q * 8 + jl;
    o[idx] = __float2half_rn(W[(size_t)k * 512 + col]);
}

__global__ void k_prep_glu_all(const float* __restrict__ Ws0,
                               const float* __restrict__ Ws1,
                               const float* __restrict__ Wu)
{
    int idx = blockIdx.x * 256 + threadIdx.x;
    const int N0 = 512 * 512;
    const int N1 = N0 + 512 * 256;
    const int N2 = N1 + 12 * 512 * 256;
    if (idx < N0) {
        prep_one(Ws0, 512, idx, g_W0);
    } else if (idx < N1) {
        prep_one(Ws1, 256, idx - N0, g_W1);
    } else if (idx < N2) {
        int r = idx - N1;
        int mi = r / (512 * 256);
        int li = r - mi * (512 * 256);
        prep_one(Wu + (size_t)mi * 256 * 512, 256, li, g_WU + (size_t)mi * 512 * 256);
    }
}

__global__ void k_prep_att_bn(const float* __restrict__ Wa,
                              const float* __restrict__ fg, const float* __restrict__ fb,
                              const float* __restrict__ fm, const float* __restrict__ fv,
                              const float* __restrict__ ag, const float* __restrict__ ab,
                              const float* __restrict__ am, const float* __restrict__ av)
{
    int idx = blockIdx.x * 256 + threadIdx.x;
    if (idx < 5 * 512 * 128) {
        int s = idx / (512 * 128);
        int r = idx - s * 512 * 128;
        int n = r >> 7, k = r & 127;
        g_WA[idx] = __float2half_rn(Wa[(size_t)s * 128 * 512 + (size_t)k * 512 + n]);
    }
    if (idx < 6 * 4 * 512) {
        float s = fg[idx] * rsqrtf(fv[idx] + EPSBN);
        g_fts[idx] = s;
        g_ftt[idx] = fb[idx] - fm[idx] * s;
    }
    if (idx < 5 * 512) {
        float s = ag[idx] * rsqrtf(av[idx] + EPSBN);
        g_as[idx] = s;
        g_at[idx] = ab[idx] - am[idx] * s;
    }
}

__global__ void k_init(const float* __restrict__ feat,
                       const float* __restrict__ g, const float* __restrict__ b,
                       const float* __restrict__ m, const float* __restrict__ v)
{
    int i = blockIdx.x * blockDim.x + threadIdx.x;
    if (i < BATCH * FDIM) {
        int c = i & (FDIM - 1);
        float f = g[c] * (feat[i] - m[c]) * rsqrtf(v[c] + EPSBN) + b[c];
        fp16 h = __float2half_rn(f);
        g_featsh[i] = h;
        g_A[i] = h;
        g_prior[i] = 1.0f;
        if (i < BATCH * OUTD) g_acc[i] = 0.0f;
    }
}

// ---------------- HMMA GEMM: MODE 0 = GLU, MODE 1 = attention ----------------
// 128 threads, 4 CTAs/SM. BM=64, BN=128, BK=64. Warp grid 2(M)x2(N), warp tile 32x64.
// 2-stage cp.async ring, ONE barrier per chunk.
#define STAGE_BYTES 24576     // A 8K | B 16K
#define NSTAGE 2
#define PARAM_OFF   (NSTAGE * STAGE_BYTES)
#define SMEM_TOTAL  (PARAM_OFF + 1024)

template<int MODE>
__global__ __launch_bounds__(128, 4)
void k_mma(const fp16* __restrict__ A, int lda, int K,
           const fp16* __restrict__ B,
           const float* __restrict__ bs, const float* __restrict__ bt,
           const fp16* __restrict__ resh,
           fp16* __restrict__ outh,
           float* __restrict__ accp,
           const float* __restrict__ prior, float* __restrict__ zout)
{
    extern __shared__ __align__(128) char smem[];
    const int tid = threadIdx.x, wid = tid >> 5, lid = tid & 31;
    const int wm = wid >> 1, wn = wid & 1;
    const int g = blockIdx.x;
    const int row0 = blockIdx.y * 64;
    const uint32_t sb = smem_u32(smem);

    // stage fused-BN params (128 prepped / CTA)
    {
        float* sE = (float*)(smem + PARAM_OFF);
        float* tE = (float*)(smem + PARAM_OFF + 512);
        int col;
        if (MODE == 0) {
            int q2 = tid >> 4, rr = tid & 15, half = rr >> 3, jl = rr & 7;
            col = (half ? 256 : 0) + g * 64 + q2 * 8 + jl;
        } else {
            col = g * 128 + tid;
        }
        sE[tid] = bs[col];
        tE[tid] = bt[col];
    }

    float acc[16][4];
#pragma unroll
    for (int i = 0; i < 16; i++)
#pragma unroll
        for (int j = 0; j < 4; j++) acc[i][j] = 0.0f;

    const int nch = K >> 6;

    // per-thread load indices: A 4 pieces, B 8 pieces
    const char* gA[4];
    const char* gB[8];
    uint32_t soA[4], soB[8];
#pragma unroll
    for (int i = 0; i < 4; i++) {
        int idx = tid + i * 128;
        int r = idx >> 3, c = idx & 7;
        soA[i] = (uint32_t)(r * 128 + ((c ^ (r & 7)) << 4));
        gA[i] = (const char*)(A + (size_t)(row0 + r) * lda + c * 8);
    }
#pragma unroll
    for (int i = 0; i < 8; i++) {
        int idx = tid + i * 128;
        int r = idx >> 3, c = idx & 7;
        soB[i] = (uint32_t)(8192 + r * 128 + ((c ^ (r & 7)) << 4));
        gB[i] = (const char*)(B + (size_t)(g * 128 + r) * K + c * 8);
    }

    auto load_stage = [&](int ch) {
        const uint32_t st = sb + (ch & 1) * STAGE_BYTES;
        const int kb = ch << 7;
#pragma unroll
        for (int i = 0; i < 4; i++) cpa16(st + soA[i], gA[i] + kb);
#pragma unroll
        for (int i = 0; i < 8; i++) cpa16(st + soB[i], gB[i] + kb);
    };

    load_stage(0);
    cpa_commit();

    const int lr = lid & 15, lc = lid >> 4;
    uint32_t offA[2], offB4[4];
#pragma unroll
    for (int m = 0; m < 2; m++) {
        int r = wm * 32 + m * 16 + lr;
        offA[m] = (uint32_t)(r * 128 + ((lc ^ (r & 7)) << 4));
    }
#pragma unroll
    for (int nb = 0; nb < 4; nb++) {
        int r = wn * 64 + nb * 16 + lr;
        offB4[nb] = (uint32_t)(8192 + r * 128 + ((lc ^ (r & 7)) << 4));
    }

    for (int ch = 0; ch < nch; ch++) {
        cpa_wait<0>();        // only stage ch is pending -> drains it
        __syncthreads();      // stage ch visible to all; everyone done reading stage ch-1
        if (ch + 1 < nch) { load_stage(ch + 1); cpa_commit(); }

        const uint32_t st = sb + (ch & 1) * STAGE_BYTES;
        uint32_t aH0 = st + offA[0], aH1 = st + offA[1];
        uint32_t aB0 = st + offB4[0], aB1 = st + offB4[1];
        uint32_t aB2 = st + offB4[2], aB3 = st + offB4[3];

#pragma unroll
        for (int ks = 0; ks < 4; ks++) {
            uint32_t ah[2][4], bq[4][4];
            ldm4(ah[0], aH0); ldm4(ah[1], aH1);
            ldm4(bq[0], aB0); ldm4(bq[1], aB1);
            ldm4(bq[2], aB2); ldm4(bq[3], aB3);
#pragma unroll
            for (int nb = 0; nb < 4; nb++)
#pragma unroll
                for (int m = 0; m < 2; m++) {
                    mma16(acc[m * 8 + 2 * nb],     ah[m], bq[nb][0], bq[nb][2]);
                    mma16(acc[m * 8 + 2 * nb + 1], ah[m], bq[nb][1], bq[nb][3]);
                }
            const uint32_t d = (ks & 1) ? 96u : 32u;
            aH0 ^= d; aH1 ^= d;
            aB0 ^= d; aB1 ^= d; aB2 ^= d; aB3 ^= d;
        }
        // no trailing barrier: next iteration's post-wait barrier protects the ring
    }
    __syncthreads();

    // ---------------- epilogue ----------------
    const float* sE = (const float*)(smem + PARAM_OFF);
    const float* tE = (const float*)(smem + PARAM_OFF + 512);
    const int gid = lid >> 2, tp = lid & 3;

    if (MODE == 0) {
#pragma unroll
        for (int m = 0; m < 2; m++) {
#pragma unroll
            for (int t = 0; t < 4; t++) {
                const int ja = wn * 64 + t * 16 + tp * 2;   // prepped local a idx
                const int jb = ja + 8;                      // paired b idx
                const int cn = g * 64 + (wn * 4 + t) * 8 + tp * 2;  // output col
                const float sa0 = sE[ja], sa1 = sE[ja + 1];
                const float ta0 = tE[ja], ta1 = tE[ja + 1];
                const float sb0 = sE[jb], sb1 = sE[jb + 1];
                const float tb0 = tE[jb], tb1 = tE[jb + 1];
                const float* ca = acc[m * 8 + 2 * t];
                const float* cb = acc[m * 8 + 2 * t + 1];
#pragma unroll
                for (int h = 0; h < 2; h++) {
                    const int row = row0 + wm * 32 + m * 16 + gid + h * 8;
                    float xa0 = ca[2 * h] * sa0 + ta0;
                    float xa1 = ca[2 * h + 1] * sa1 + ta1;
                    float xb0 = cb[2 * h] * sb0 + tb0;
                    float xb1 = cb[2 * h + 1] * sb1 + tb1;
                    float o0 = xa0 * (1.0f / (1.0f + __expf(-xb0)));
                    float o1 = xa1 * (1.0f / (1.0f + __expf(-xb1)));
                    const size_t ob = (size_t)row * HS + cn;
                    if (resh) {
                        __half2 rh = *(const __half2*)(resh + ob);
                        o0 = fmaf(__half2float(rh.x), 0.70710678118654752f, o0);
                        o1 = fmaf(__half2float(rh.y), 0.70710678118654752f, o1);
                    }
                    __half2 hh;
                    hh.x = __float2half_rn(o0);
                    hh.y = __float2half_rn(o1);
                    *(__half2*)(outh + ob) = hh;
                    if (accp && g < 2) {
                        float2* ap = (float2*)(accp + (size_t)row * OUTD + cn);
                        float2 av = *ap;
                        av.x += fmaxf(o0, 0.0f);
                        av.y += fmaxf(o1, 0.0f);
                        *ap = av;
                    }
                }
            }
        }
    } else {
#pragma unroll
        for (int m = 0; m < 2; m++) {
#pragma unroll
            for (int nb2 = 0; nb2 < 8; nb2++) {
                const int cn = wn * 64 + nb2 * 8 + tp * 2;
                const float s0 = sE[cn], s1 = sE[cn + 1];
                const float t0 = tE[cn], t1 = tE[cn + 1];
                const float* ca = acc[m * 8 + nb2];
#pragma unroll
                for (int h = 0; h < 2; h++) {
                    const int row = row0 + wm * 32 + m * 16 + gid + h * 8;
                    const size_t idx = (size_t)row * FDIM + g * 128 + cn;
                    float2 pr = *(const float2*)(prior + idx);
                    float2 zz;
                    zz.x = (ca[2 * h] * s0 + t0) * pr.x;
                    zz.y = (ca[2 * h + 1] * s1 + t1) * pr.y;
                    *(float2*)(zout + idx) = zz;
                }
            }
        }
    }
}

// ---------------- sparsemax: one warp per row ----------------
__global__ __launch_bounds__(256)
void k_sparsemax(const float* __restrict__ z, float* __restrict__ prior,
                 float* __restrict__ maskOut, fp16* __restrict__ mf)
{
    const int row = blockIdx.x * 8 + (threadIdx.x >> 5);
    const int lid = threadIdx.x & 31;
    const size_t base = (size_t)row * 512;
    float v[16];
#pragma unroll
    for (int q = 0; q < 4; q++) {
        float4 t = *(const float4*)(z + base + q * 128 + lid * 4);
        v[q * 4 + 0] = t.x; v[q * 4 + 1] = t.y; v[q * 4 + 2] = t.z; v[q * 4 + 3] = t.w;
    }
    float zmax = v[0];
#pragma unroll
    for (int i = 1; i < 16; i++) zmax = fmaxf(zmax, v[i]);
#pragma unroll
    for (int o = 16; o; o >>= 1) zmax = fmaxf(zmax, __shfl_xor_sync(0xffffffffu, zmax, o));

    float lo = zmax - 1.0f, hi = zmax;
    for (int it = 0; it < 20; it++) {
        float mid = 0.5f * (lo + hi);
        float s = 0.0f;
#pragma unroll
        for (int i = 0; i < 16; i++) s += fmaxf(v[i] - mid, 0.0f);
#pragma unroll
        for (int o = 16; o; o >>= 1) s += __shfl_xor_sync(0xffffffffu, s, o);
        if (s >= 1.0f) lo = mid; else hi = mid;
    }
    float sum = 0.0f, cnt = 0.0f;
#pragma unroll
    for (int i = 0; i < 16; i++) {
        if (v[i] > lo) { sum += v[i]; cnt += 1.0f; }
    }
#pragma unroll
    for (int o = 16; o; o >>= 1) {
        sum += __shfl_xor_sync(0xffffffffu, sum, o);
        cnt += __shfl_xor_sync(0xffffffffu, cnt, o);
    }
    const float tau = (sum - 1.0f) / cnt;

#pragma unroll
    for (int q = 0; q < 4; q++) {
        const size_t off = base + q * 128 + lid * 4;
        float4 mk;
        mk.x = fmaxf(v[q * 4 + 0] - tau, 0.0f);
        mk.y = fmaxf(v[q * 4 + 1] - tau, 0.0f);
        mk.z = fmaxf(v[q * 4 + 2] - tau, 0.0f);
        mk.w = fmaxf(v[q * 4 + 3] - tau, 0.0f);
        *(float4*)(maskOut + off) = mk;
        float4 pr = *(const float4*)(prior + off);
        pr.x *= (1.5f - mk.x); pr.y *= (1.5f - mk.y);
        pr.z *= (1.5f - mk.z); pr.w *= (1.5f - mk.w);
        *(float4*)(prior + off) = pr;
        __half2 f01 = *(const __half2*)(g_featsh + off);
        __half2 f23 = *(const __half2*)(g_featsh + off + 2);
        __half2 p0, p1;
        p0.x = __float2half_rn(mk.x * __half2float(f01.x));
        p0.y = __float2half_rn(mk.y * __half2float(f01.y));
        p1.x = __float2half_rn(mk.z * __half2float(f23.x));
        p1.y = __float2half_rn(mk.w * __half2float(f23.y));
        *(__half2*)(mf + off) = p0;
        *(__half2*)(mf + off + 2) = p1;
    }
}

// ---------------- final projection ----------------
__global__ __launch_bounds__(256)
void k_fin(const float* __restrict__ A, const float* __restrict__ W,
           const float* __restrict__ bias, float* __restrict__ C)
{
    __shared__ float As[16][128];
    __shared__ float Ws[16][64];
    const int tid = threadIdx.x;
    const int ty = tid >> 4, tx = tid & 15;
    const int row0 = blockIdx.y * 128;
    const int col0 = blockIdx.x * 64;

    float acc[8][4];
#pragma unroll
    for (int r = 0; r < 8; r++)
#pragma unroll
        for (int c = 0; c < 4; c++) acc[r][c] = 0.f;

    for (int kt = 0; kt < 128; kt += 16) {
#pragma unroll
        for (int l = 0; l < 2; l++) {
            int li = tid * 2 + l;
            int r = li >> 2, kq = (li & 3) * 4;
            float4 av = *(const float4*)(A + (size_t)(row0 + r) * 128 + kt + kq);
            As[kq + 0][r] = av.x; As[kq + 1][r] = av.y;
            As[kq + 2][r] = av.z; As[kq + 3][r] = av.w;
        }
        *(float4*)&Ws[tid >> 4][(tid & 15) * 4] =
            *(const float4*)(W + (size_t)(kt + (tid >> 4)) * 128 + col0 + (tid & 15) * 4);
        __syncthreads();
#pragma unroll
        for (int kk = 0; kk < 16; kk++) {
            float a[8];
            float4 a0 = *(float4*)&As[kk][ty * 8];
            float4 a1 = *(float4*)&As[kk][ty * 8 + 4];
            a[0] = a0.x; a[1] = a0.y; a[2] = a0.z; a[3] = a0.w;
            a[4] = a1.x; a[5] = a1.y; a[6] = a1.z; a[7] = a1.w;
            float4 w0 = *(float4*)&Ws[kk][tx * 4];
            float wv[4] = {w0.x, w0.y, w0.z, w0.w};
#pragma unroll
            for (int r = 0; r < 8; r++)
#pragma unroll
                for (int c = 0; c < 4; c++) acc[r][c] += a[r] * wv[c];
        }
        __syncthreads();
    }
#pragma unroll
    for (int r = 0; r < 8; r++) {
        int gr = row0 + ty * 8 + r;
#pragma unroll
        for (int c = 0; c < 4; c++) {
            int gc = col0 + tx * 4 + c;
            C[(size_t)gr * 128 + gc] = acc[r][c] + bias[gc];
        }
    }
}

// ---------------- launch ----------------
extern "C" void kernel_launch(void* const* d_in, const int* in_sizes, int n_in,
                              void* d_out, int out_size)
{
    const float* features = (const float*)d_in[0];
    const float* bn0_g = (const float*)d_in[1];
    const float* bn0_b = (const float*)d_in[2];
    const float* bn0_m = (const float*)d_in[3];
    const float* bn0_v = (const float*)d_in[4];
    const float* Ws0   = (const float*)d_in[5];
    const float* Ws1   = (const float*)d_in[6];
    const float* Wu    = (const float*)d_in[7];
    const float* ft_g  = (const float*)d_in[8];
    const float* ft_b  = (const float*)d_in[9];
    const float* ft_m  = (const float*)d_in[10];
    const float* ft_v  = (const float*)d_in[11];
    const float* W_att = (const float*)d_in[12];
    const float* att_g = (const float*)d_in[13];
    const float* att_b = (const float*)d_in[14];
    const float* att_m = (const float*)d_in[15];
    const float* att_v = (const float*)d_in[16];
    const float* Wf    = (const float*)d_in[17];
    const float* bf    = (const float*)d_in[18];

    float *zp, *prior, *acc;
    fp16 *A, *h0, *h1;
    fp16 *W0, *W1, *WU, *WA;
    float *fts, *ftt, *as, *at;
    cudaGetSymbolAddress((void**)&A, g_A);
    cudaGetSymbolAddress((void**)&h0, g_h0);
    cudaGetSymbolAddress((void**)&h1, g_h1);
    cudaGetSymbolAddress((void**)&zp, g_z);
    cudaGetSymbolAddress((void**)&prior, g_prior);
    cudaGetSymbolAddress((void**)&acc, g_acc);
    cudaGetSymbolAddress((void**)&W0, g_W0);
    cudaGetSymbolAddress((void**)&W1, g_W1);
    cudaGetSymbolAddress((void**)&WU, g_WU);
    cudaGetSymbolAddress((void**)&WA, g_WA);
    cudaGetSymbolAddress((void**)&fts, g_fts);
    cudaGetSymbolAddress((void**)&ftt, g_ftt);
    cudaGetSymbolAddress((void**)&as, g_as);
    cudaGetSymbolAddress((void**)&at, g_at);

    float* outF  = (float*)d_out;
    float* masks = outF + (size_t)BATCH * OUTD;

    static bool attr_set = false;
    if (!attr_set) {
        cudaFuncSetAttribute(k_mma<0>, cudaFuncAttributeMaxDynamicSharedMemorySize, SMEM_TOTAL);
        cudaFuncSetAttribute(k_mma<1>, cudaFuncAttributeMaxDynamicSharedMemorySize, SMEM_TOTAL);
        attr_set = true;
    }

    const int PREP_N = 512 * 512 + 512 * 256 + 12 * 512 * 256;
    k_prep_glu_all<<<(PREP_N + 255) / 256, 256>>>(Ws0, Ws1, Wu);
    k_prep_att_bn<<<(5 * 512 * 128 + 255) / 256, 256>>>(W_att, ft_g, ft_b, ft_m, ft_v,
                                                        att_g, att_b, att_m, att_v);
    k_init<<<(BATCH * FDIM) / 256, 256>>>(features, bn0_g, bn0_b, bn0_m, bn0_v);

    const dim3 gMma(4, BATCH / 64);

    auto ft_transformer = [&](int t, float* accOut) {
        const float* s0 = fts + (size_t)t * 4 * 512;
        const float* t0 = ftt + (size_t)t * 4 * 512;
        k_mma<0><<<gMma, 128, SMEM_TOTAL>>>(A, 512, 512, W0,
            s0, t0, nullptr, h0, nullptr, nullptr, nullptr);
        k_mma<0><<<gMma, 128, SMEM_TOTAL>>>(h0, 256, 256, W1,
            s0 + 512, t0 + 512, h0, h1, nullptr, nullptr, nullptr);
        k_mma<0><<<gMma, 128, SMEM_TOTAL>>>(h1, 256, 256,
            WU + (size_t)(t * 2 + 0) * 512 * 256,
            s0 + 1024, t0 + 1024, h1, h0, nullptr, nullptr, nullptr);
        k_mma<0><<<gMma, 128, SMEM_TOTAL>>>(h0, 256, 256,
            WU + (size_t)(t * 2 + 1) * 512 * 256,
            s0 + 1536, t0 + 1536, h0, h1, accOut, nullptr, nullptr);
    };

    ft_transformer(0, nullptr);

    for (int s = 0; s < STEPS; s++) {
        k_mma<1><<<gMma, 128, SMEM_TOTAL>>>(h1 + 128, 256, 128,
            WA + (size_t)s * 512 * 128,
            as + (size_t)s * 512, at + (size_t)s * 512,
            nullptr, nullptr, nullptr,
            prior, zp);
        k_sparsemax<<<BATCH / 8, 256>>>(zp, prior, masks + (size_t)s * BATCH * FDIM, A);
        ft_transformer(s + 1, acc);
    }

    k_fin<<<dim3(2, BATCH / 128), 256>>>(acc, Wf, bf, outF);
}

// round 11
// speedup vs baseline: 1.0526x; 1.0526x over previous
#include <cuda_runtime.h>
#include <cuda_fp16.h>
#include <math.h>
#include <stdint.h>

#define BATCH 32768
#define FDIM 512
#define HS 256
#define OUTD 128
#define STEPS 5
#define EPSBN 1e-5f

typedef __half fp16;

// ---------------- scratch (device globals; no allocation) ----------------
__device__ fp16  g_featsh[BATCH * FDIM];
__device__ fp16  g_A[BATCH * FDIM];
__device__ fp16  g_h0[BATCH * HS];
__device__ fp16  g_h1[BATCH * HS];
__device__ float g_z[BATCH * FDIM];
__device__ float g_prior[BATCH * FDIM];
__device__ float g_acc[BATCH * OUTD];

// prepped weights ([N,K] fp16; GLU ones N-permuted with 8-col a/b interleave)
__device__ fp16 g_W0[512 * 512];
__device__ fp16 g_W1[512 * 256];
__device__ fp16 g_WU[12 * 512 * 256];
__device__ fp16 g_WA[5 * 512 * 128];
__device__ float g_fts[6 * 4 * 512], g_ftt[6 * 4 * 512];
__device__ float g_as[5 * 512], g_at[5 * 512];

// ---------------- PTX helpers ----------------
__device__ __forceinline__ uint32_t smem_u32(const void* p) {
    uint32_t a;
    asm("{ .reg .u64 t; cvta.to.shared.u64 t, %1; cvt.u32.u64 %0, t; }" : "=r"(a) : "l"(p));
    return a;
}
__device__ __forceinline__ void cpa16(uint32_t s, const void* g) {
    asm volatile("cp.async.cg.shared.global [%0], [%1], 16;" :: "r"(s), "l"(g));
}
__device__ __forceinline__ void cpa_commit() {
    asm volatile("cp.async.commit_group;" ::: "memory");
}
template<int N>
__device__ __forceinline__ void cpa_wait() {
    asm volatile("cp.async.wait_group %0;" :: "n"(N) : "memory");
}
__device__ __forceinline__ void ldm4(uint32_t* v, uint32_t addr) {
    asm volatile("ldmatrix.sync.aligned.m8n8.x4.shared.b16 {%0,%1,%2,%3}, [%4];"
                 : "=r"(v[0]), "=r"(v[1]), "=r"(v[2]), "=r"(v[3]) : "r"(addr));
}
__device__ __forceinline__ void mma16(float* c, const uint32_t* a, uint32_t b0, uint32_t b1) {
    asm("mma.sync.aligned.m16n8k16.row.col.f32.f16.f16.f32 "
        "{%0,%1,%2,%3}, {%4,%5,%6,%7}, {%8,%9}, {%0,%1,%2,%3};"
        : "+f"(c[0]), "+f"(c[1]), "+f"(c[2]), "+f"(c[3])
        : "r"(a[0]), "r"(a[1]), "r"(a[2]), "r"(a[3]), "r"(b0), "r"(b1));
}

// ---------------- prep ----------------
__device__ __forceinline__ void prep_one(const float* W, int K, int idx, fp16* o)
{
    int n = idx / K, k = idx - n * K;
    int q = n >> 4, rr = n & 15, half = rr >> 3, jl = rr & 7;
    int col = (half ? 256 : 0) + q * 8 + jl;
    o[idx] = __float2half_rn(W[(size_t)k * 512 + col]);
}

__global__ void k_prep_glu_all(const float* __restrict__ Ws0,
                               const float* __restrict__ Ws1,
                               const float* __restrict__ Wu)
{
    int idx = blockIdx.x * 256 + threadIdx.x;
    const int N0 = 512 * 512;
    const int N1 = N0 + 512 * 256;
    const int N2 = N1 + 12 * 512 * 256;
    if (idx < N0) {
        prep_one(Ws0, 512, idx, g_W0);
    } else if (idx < N1) {
        prep_one(Ws1, 256, idx - N0, g_W1);
    } else if (idx < N2) {
        int r = idx - N1;
        int mi = r / (512 * 256);
        int li = r - mi * (512 * 256);
        prep_one(Wu + (size_t)mi * 256 * 512, 256, li, g_WU + (size_t)mi * 512 * 256);
    }
}

__global__ void k_prep_att_bn(const float* __restrict__ Wa,
                              const float* __restrict__ fg, const float* __restrict__ fb,
                              const float* __restrict__ fm, const float* __restrict__ fv,
                              const float* __restrict__ ag, const float* __restrict__ ab,
                              const float* __restrict__ am, const float* __restrict__ av)
{
    int idx = blockIdx.x * 256 + threadIdx.x;
    if (idx < 5 * 512 * 128) {
        int s = idx / (512 * 128);
        int r = idx - s * 512 * 128;
        int n = r >> 7, k = r & 127;
        g_WA[idx] = __float2half_rn(Wa[(size_t)s * 128 * 512 + (size_t)k * 512 + n]);
    }
    if (idx < 6 * 4 * 512) {
        float s = fg[idx] * rsqrtf(fv[idx] + EPSBN);
        g_fts[idx] = s;
        g_ftt[idx] = fb[idx] - fm[idx] * s;
    }
    if (idx < 5 * 512) {
        float s = ag[idx] * rsqrtf(av[idx] + EPSBN);
        g_as[idx] = s;
        g_at[idx] = ab[idx] - am[idx] * s;
    }
}

__global__ void k_init(const float* __restrict__ feat,
                       const float* __restrict__ g, const float* __restrict__ b,
                       const float* __restrict__ m, const float* __restrict__ v)
{
    int i = blockIdx.x * blockDim.x + threadIdx.x;
    if (i < BATCH * FDIM) {
        int c = i & (FDIM - 1);
        float f = g[c] * (feat[i] - m[c]) * rsqrtf(v[c] + EPSBN) + b[c];
        fp16 h = __float2half_rn(f);
        g_featsh[i] = h;
        g_A[i] = h;
        g_prior[i] = 1.0f;
        if (i < BATCH * OUTD) g_acc[i] = 0.0f;
    }
}

// ---------------- HMMA GEMM: MODE 0 = GLU, MODE 1 = attention ----------------
// 256 threads, 2 CTAs/SM. BM=128, BN=128, BK=64. Warp grid 4(M)x2(N), warp tile 32x64.
// 3-stage cp.async ring, ONE barrier per chunk.
#define STAGE_BYTES 32768     // A 16K | B 16K
#define NSTAGE 3
#define PARAM_OFF   (NSTAGE * STAGE_BYTES)
#define SMEM_TOTAL  (PARAM_OFF + 1024)

template<int MODE>
__global__ __launch_bounds__(256, 2)
void k_mma(const fp16* __restrict__ A, int lda, int K,
           const fp16* __restrict__ B,
           const float* __restrict__ bs, const float* __restrict__ bt,
           const fp16* __restrict__ resh,
           fp16* __restrict__ outh,
           float* __restrict__ accp,
           const float* __restrict__ prior, float* __restrict__ zout)
{
    extern __shared__ __align__(128) char smem[];
    const int tid = threadIdx.x, wid = tid >> 5, lid = tid & 31;
    const int wm = wid >> 1, wn = wid & 1;
    const int g = blockIdx.x;
    const int row0 = blockIdx.y * 128;
    const uint32_t sb = smem_u32(smem);

    // stage fused-BN params (128 per CTA)
    if (tid < 128) {
        float* sE = (float*)(smem + PARAM_OFF);
        float* tE = (float*)(smem + PARAM_OFF + 512);
        int col;
        if (MODE == 0) {
            int q2 = tid >> 4, rr = tid & 15, half = rr >> 3, jl = rr & 7;
            col = (half ? 256 : 0) + g * 64 + q2 * 8 + jl;
        } else {
            col = g * 128 + tid;
        }
        sE[tid] = bs[col];
        tE[tid] = bt[col];
    }

    float acc[16][4];
#pragma unroll
    for (int i = 0; i < 16; i++)
#pragma unroll
        for (int j = 0; j < 4; j++) acc[i][j] = 0.0f;

    const int nch = K >> 6;

    // per-thread load indices: 4 A rows, 4 B rows per thread
    const char* gA[4];
    const char* gB[4];
    uint32_t soA[4], soB[4];
#pragma unroll
    for (int i = 0; i < 4; i++) {
        int idx = tid + i * 256;
        int r = idx >> 3, c = idx & 7;
        uint32_t so = (uint32_t)(r * 128 + ((c ^ (r & 7)) << 4));
        soA[i] = so;
        soB[i] = 16384u + so;
        gA[i] = (const char*)(A + (size_t)(row0 + r) * lda + c * 8);
        gB[i] = (const char*)(B + (size_t)(g * 128 + r) * K + c * 8);
    }

    auto load_stage = [&](int ch) {
        const uint32_t st = sb + (ch % NSTAGE) * STAGE_BYTES;
        const int kb = ch << 7;
#pragma unroll
        for (int i = 0; i < 4; i++) {
            cpa16(st + soA[i], gA[i] + kb);
            cpa16(st + soB[i], gB[i] + kb);
        }
    };

    // prologue: 2 groups
#pragma unroll
    for (int p = 0; p < 2; p++) {
        if (p < nch) load_stage(p);
        cpa_commit();
    }

    const int lr = lid & 15, lc = lid >> 4;
    uint32_t offA[2], offB4[4];
#pragma unroll
    for (int m = 0; m < 2; m++) {
        int r = wm * 32 + m * 16 + lr;
        offA[m] = (uint32_t)(r * 128 + ((lc ^ (r & 7)) << 4));
    }
#pragma unroll
    for (int nb = 0; nb < 4; nb++) {
        int r = wn * 64 + nb * 16 + lr;
        offB4[nb] = (uint32_t)(16384 + r * 128 + ((lc ^ (r & 7)) << 4));
    }

    for (int ch = 0; ch < nch; ch++) {
        cpa_wait<1>();
        __syncthreads();   // stage ch visible; all warps done with chunk ch-1
        if (ch + 2 < nch) load_stage(ch + 2);
        cpa_commit();

        const uint32_t st = sb + (ch % NSTAGE) * STAGE_BYTES;
        uint32_t aH0 = st + offA[0], aH1 = st + offA[1];
        uint32_t aB0 = st + offB4[0], aB1 = st + offB4[1];
        uint32_t aB2 = st + offB4[2], aB3 = st + offB4[3];

#pragma unroll
        for (int ks = 0; ks < 4; ks++) {
            uint32_t ah[2][4], bq[4][4];
            ldm4(ah[0], aH0); ldm4(ah[1], aH1);
            ldm4(bq[0], aB0); ldm4(bq[1], aB1);
            ldm4(bq[2], aB2); ldm4(bq[3], aB3);
#pragma unroll
            for (int nb = 0; nb < 4; nb++)
#pragma unroll
                for (int m = 0; m < 2; m++) {
                    mma16(acc[m * 8 + 2 * nb],     ah[m], bq[nb][0], bq[nb][2]);
                    mma16(acc[m * 8 + 2 * nb + 1], ah[m], bq[nb][1], bq[nb][3]);
                }
            const uint32_t d = (ks & 1) ? 96u : 32u;
            aH0 ^= d; aH1 ^= d;
            aB0 ^= d; aB1 ^= d; aB2 ^= d; aB3 ^= d;
        }
        // no trailing barrier: next chunk's post-wait barrier protects the ring
        // (load_stage(ch+2) overwrites slot (ch-1)%3, fully read before this
        //  iteration's leading barrier)
    }
    // no pre-epilogue barrier: epilogue reads only regs + pre-loop smem params

    // ---------------- epilogue ----------------
    const float* sE = (const float*)(smem + PARAM_OFF);
    const float* tE = (const float*)(smem + PARAM_OFF + 512);
    const int gid = lid >> 2, tp = lid & 3;

    if (MODE == 0) {
#pragma unroll
        for (int m = 0; m < 2; m++) {
#pragma unroll
            for (int t = 0; t < 4; t++) {
                const int ja = wn * 64 + t * 16 + tp * 2;   // prepped local a idx
                const int jb = ja + 8;                      // paired b idx
                const int cn = g * 64 + (wn * 4 + t) * 8 + tp * 2;  // output col
                const float sa0 = sE[ja], sa1 = sE[ja + 1];
                const float ta0 = tE[ja], ta1 = tE[ja + 1];
                const float sb0 = sE[jb], sb1 = sE[jb + 1];
                const float tb0 = tE[jb], tb1 = tE[jb + 1];
                const float* ca = acc[m * 8 + 2 * t];
                const float* cb = acc[m * 8 + 2 * t + 1];
#pragma unroll
                for (int h = 0; h < 2; h++) {
                    const int row = row0 + wm * 32 + m * 16 + gid + h * 8;
                    float xa0 = ca[2 * h] * sa0 + ta0;
                    float xa1 = ca[2 * h + 1] * sa1 + ta1;
                    float xb0 = cb[2 * h] * sb0 + tb0;
                    float xb1 = cb[2 * h + 1] * sb1 + tb1;
                    float o0 = xa0 * (1.0f / (1.0f + __expf(-xb0)));
                    float o1 = xa1 * (1.0f / (1.0f + __expf(-xb1)));
                    const size_t ob = (size_t)row * HS + cn;
                    if (resh) {
                        __half2 rh = *(const __half2*)(resh + ob);
                        o0 = fmaf(__half2float(rh.x), 0.70710678118654752f, o0);
                        o1 = fmaf(__half2float(rh.y), 0.70710678118654752f, o1);
                    }
                    __half2 hh;
                    hh.x = __float2half_rn(o0);
                    hh.y = __float2half_rn(o1);
                    *(__half2*)(outh + ob) = hh;
                    if (accp && g < 2) {
                        float2* ap = (float2*)(accp + (size_t)row * OUTD + cn);
                        float2 av = *ap;
                        av.x += fmaxf(o0, 0.0f);
                        av.y += fmaxf(o1, 0.0f);
                        *ap = av;
                    }
                }
            }
        }
    } else {
#pragma unroll
        for (int m = 0; m < 2; m++) {
#pragma unroll
            for (int nb2 = 0; nb2 < 8; nb2++) {
                const int cn = wn * 64 + nb2 * 8 + tp * 2;
                const float s0 = sE[cn], s1 = sE[cn + 1];
                const float t0 = tE[cn], t1 = tE[cn + 1];
                const float* ca = acc[m * 8 + nb2];
#pragma unroll
                for (int h = 0; h < 2; h++) {
                    const int row = row0 + wm * 32 + m * 16 + gid + h * 8;
                    const size_t idx = (size_t)row * FDIM + g * 128 + cn;
                    float2 pr = *(const float2*)(prior + idx);
                    float2 zz;
                    zz.x = (ca[2 * h] * s0 + t0) * pr.x;
                    zz.y = (ca[2 * h + 1] * s1 + t1) * pr.y;
                    *(float2*)(zout + idx) = zz;
                }
            }
        }
    }
}

// ---------------- sparsemax: one warp per row ----------------
__global__ __launch_bounds__(256)
void k_sparsemax(const float* __restrict__ z, float* __restrict__ prior,
                 float* __restrict__ maskOut, fp16* __restrict__ mf)
{
    const int row = blockIdx.x * 8 + (threadIdx.x >> 5);
    const int lid = threadIdx.x & 31;
    const size_t base = (size_t)row * 512;
    float v[16];
#pragma unroll
    for (int q = 0; q < 4; q++) {
        float4 t = *(const float4*)(z + base + q * 128 + lid * 4);
        v[q * 4 + 0] = t.x; v[q * 4 + 1] = t.y; v[q * 4 + 2] = t.z; v[q * 4 + 3] = t.w;
    }
    float zmax = v[0];
#pragma unroll
    for (int i = 1; i < 16; i++) zmax = fmaxf(zmax, v[i]);
#pragma unroll
    for (int o = 16; o; o >>= 1) zmax = fmaxf(zmax, __shfl_xor_sync(0xffffffffu, zmax, o));

    float lo = zmax - 1.0f, hi = zmax;
    for (int it = 0; it < 20; it++) {
        float mid = 0.5f * (lo + hi);
        float s = 0.0f;
#pragma unroll
        for (int i = 0; i < 16; i++) s += fmaxf(v[i] - mid, 0.0f);
#pragma unroll
        for (int o = 16; o; o >>= 1) s += __shfl_xor_sync(0xffffffffu, s, o);
        if (s >= 1.0f) lo = mid; else hi = mid;
    }
    float sum = 0.0f, cnt = 0.0f;
#pragma unroll
    for (int i = 0; i < 16; i++) {
        if (v[i] > lo) { sum += v[i]; cnt += 1.0f; }
    }
#pragma unroll
    for (int o = 16; o; o >>= 1) {
        sum += __shfl_xor_sync(0xffffffffu, sum, o);
        cnt += __shfl_xor_sync(0xffffffffu, cnt, o);
    }
    const float tau = (sum - 1.0f) / cnt;

#pragma unroll
    for (int q = 0; q < 4; q++) {
        const size_t off = base + q * 128 + lid * 4;
        float4 mk;
        mk.x = fmaxf(v[q * 4 + 0] - tau, 0.0f);
        mk.y = fmaxf(v[q * 4 + 1] - tau, 0.0f);
        mk.z = fmaxf(v[q * 4 + 2] - tau, 0.0f);
        mk.w = fmaxf(v[q * 4 + 3] - tau, 0.0f);
        *(float4*)(maskOut + off) = mk;
        float4 pr = *(const float4*)(prior + off);
        pr.x *= (1.5f - mk.x); pr.y *= (1.5f - mk.y);
        pr.z *= (1.5f - mk.z); pr.w *= (1.5f - mk.w);
        *(float4*)(prior + off) = pr;
        __half2 f01 = *(const __half2*)(g_featsh + off);
        __half2 f23 = *(const __half2*)(g_featsh + off + 2);
        __half2 p0, p1;
        p0.x = __float2half_rn(mk.x * __half2float(f01.x));
        p0.y = __float2half_rn(mk.y * __half2float(f01.y));
        p1.x = __float2half_rn(mk.z * __half2float(f23.x));
        p1.y = __float2half_rn(mk.w * __half2float(f23.y));
        *(__half2*)(mf + off) = p0;
        *(__half2*)(mf + off + 2) = p1;
    }
}

// ---------------- final projection ----------------
__global__ __launch_bounds__(256)
void k_fin(const float* __restrict__ A, const float* __restrict__ W,
           const float* __restrict__ bias, float* __restrict__ C)
{
    __shared__ float As[16][128];
    __shared__ float Ws[16][64];
    const int tid = threadIdx.x;
    const int ty = tid >> 4, tx = tid & 15;
    const int row0 = blockIdx.y * 128;
    const int col0 = blockIdx.x * 64;

    float acc[8][4];
#pragma unroll
    for (int r = 0; r < 8; r++)
#pragma unroll
        for (int c = 0; c < 4; c++) acc[r][c] = 0.f;

    for (int kt = 0; kt < 128; kt += 16) {
#pragma unroll
        for (int l = 0; l < 2; l++) {
            int li = tid * 2 + l;
            int r = li >> 2, kq = (li & 3) * 4;
            float4 av = *(const float4*)(A + (size_t)(row0 + r) * 128 + kt + kq);
            As[kq + 0][r] = av.x; As[kq + 1][r] = av.y;
            As[kq + 2][r] = av.z; As[kq + 3][r] = av.w;
        }
        *(float4*)&Ws[tid >> 4][(tid & 15) * 4] =
            *(const float4*)(W + (size_t)(kt + (tid >> 4)) * 128 + col0 + (tid & 15) * 4);
        __syncthreads();
#pragma unroll
        for (int kk = 0; kk < 16; kk++) {
            float a[8];
            float4 a0 = *(float4*)&As[kk][ty * 8];
            float4 a1 = *(float4*)&As[kk][ty * 8 + 4];
            a[0] = a0.x; a[1] = a0.y; a[2] = a0.z; a[3] = a0.w;
            a[4] = a1.x; a[5] = a1.y; a[6] = a1.z; a[7] = a1.w;
            float4 w0 = *(float4*)&Ws[kk][tx * 4];
            float wv[4] = {w0.x, w0.y, w0.z, w0.w};
#pragma unroll
            for (int r = 0; r < 8; r++)
#pragma unroll
                for (int c = 0; c < 4; c++) acc[r][c] += a[r] * wv[c];
        }
        __syncthreads();
    }
#pragma unroll
    for (int r = 0; r < 8; r++) {
        int gr = row0 + ty * 8 + r;
#pragma unroll
        for (int c = 0; c < 4; c++) {
            int gc = col0 + tx * 4 + c;
            C[(size_t)gr * 128 + gc] = acc[r][c] + bias[gc];
        }
    }
}

// ---------------- launch ----------------
extern "C" void kernel_launch(void* const* d_in, const int* in_sizes, int n_in,
                              void* d_out, int out_size)
{
    const float* features = (const float*)d_in[0];
    const float* bn0_g = (const float*)d_in[1];
    const float* bn0_b = (const float*)d_in[2];
    const float* bn0_m = (const float*)d_in[3];
    const float* bn0_v = (const float*)d_in[4];
    const float* Ws0   = (const float*)d_in[5];
    const float* Ws1   = (const float*)d_in[6];
    const float* Wu    = (const float*)d_in[7];
    const float* ft_g  = (const float*)d_in[8];
    const float* ft_b  = (const float*)d_in[9];
    const float* ft_m  = (const float*)d_in[10];
    const float* ft_v  = (const float*)d_in[11];
    const float* W_att = (const float*)d_in[12];
    const float* att_g = (const float*)d_in[13];
    const float* att_b = (const float*)d_in[14];
    const float* att_m = (const float*)d_in[15];
    const float* att_v = (const float*)d_in[16];
    const float* Wf    = (const float*)d_in[17];
    const float* bf    = (const float*)d_in[18];

    float *zp, *prior, *acc;
    fp16 *A, *h0, *h1;
    fp16 *W0, *W1, *WU, *WA;
    float *fts, *ftt, *as, *at;
    cudaGetSymbolAddress((void**)&A, g_A);
    cudaGetSymbolAddress((void**)&h0, g_h0);
    cudaGetSymbolAddress((void**)&h1, g_h1);
    cudaGetSymbolAddress((void**)&zp, g_z);
    cudaGetSymbolAddress((void**)&prior, g_prior);
    cudaGetSymbolAddress((void**)&acc, g_acc);
    cudaGetSymbolAddress((void**)&W0, g_W0);
    cudaGetSymbolAddress((void**)&W1, g_W1);
    cudaGetSymbolAddress((void**)&WU, g_WU);
    cudaGetSymbolAddress((void**)&WA, g_WA);
    cudaGetSymbolAddress((void**)&fts, g_fts);
    cudaGetSymbolAddress((void**)&ftt, g_ftt);
    cudaGetSymbolAddress((void**)&as, g_as);
    cudaGetSymbolAddress((void**)&at, g_at);

    float* outF  = (float*)d_out;
    float* masks = outF + (size_t)BATCH * OUTD;

    static bool attr_set = false;
    if (!attr_set) {
        cudaFuncSetAttribute(k_mma<0>, cudaFuncAttributeMaxDynamicSharedMemorySize, SMEM_TOTAL);
        cudaFuncSetAttribute(k_mma<1>, cudaFuncAttributeMaxDynamicSharedMemorySize, SMEM_TOTAL);
        attr_set = true;
    }

    const int PREP_N = 512 * 512 + 512 * 256 + 12 * 512 * 256;
    k_prep_glu_all<<<(PREP_N + 255) / 256, 256>>>(Ws0, Ws1, Wu);
    k_prep_att_bn<<<(5 * 512 * 128 + 255) / 256, 256>>>(W_att, ft_g, ft_b, ft_m, ft_v,
                                                        att_g, att_b, att_m, att_v);
    k_init<<<(BATCH * FDIM) / 256, 256>>>(features, bn0_g, bn0_b, bn0_m, bn0_v);

    const dim3 gMma(4, BATCH / 128);

    auto ft_transformer = [&](int t, float* accOut) {
        const float* s0 = fts + (size_t)t * 4 * 512;
        const float* t0 = ftt + (size_t)t * 4 * 512;
        k_mma<0><<<gMma, 256, SMEM_TOTAL>>>(A, 512, 512, W0,
            s0, t0, nullptr, h0, nullptr, nullptr, nullptr);
        k_mma<0><<<gMma, 256, SMEM_TOTAL>>>(h0, 256, 256, W1,
            s0 + 512, t0 + 512, h0, h1, nullptr, nullptr, nullptr);
        k_mma<0><<<gMma, 256, SMEM_TOTAL>>>(h1, 256, 256,
            WU + (size_t)(t * 2 + 0) * 512 * 256,
            s0 + 1024, t0 + 1024, h1, h0, nullptr, nullptr, nullptr);
        k_mma<0><<<gMma, 256, SMEM_TOTAL>>>(h0, 256, 256,
            WU + (size_t)(t * 2 + 1) * 512 * 256,
            s0 + 1536, t0 + 1536, h0, h1, accOut, nullptr, nullptr);
    };

    ft_transformer(0, nullptr);

    for (int s = 0; s < STEPS; s++) {
        k_mma<1><<<gMma, 256, SMEM_TOTAL>>>(h1 + 128, 256, 128,
            WA + (size_t)s * 512 * 128,
            as + (size_t)s * 512, at + (size_t)s * 512,
            nullptr, nullptr, nullptr,
            prior, zp);
        k_sparsemax<<<BATCH / 8, 256>>>(zp, prior, masks + (size_t)s * BATCH * FDIM, A);
        ft_transformer(s + 1, acc);
    }

    k_fin<<<dim3(2, BATCH / 128), 256>>>(acc, Wf, bf, outF);
}

// round 12
// speedup vs baseline: 1.0692x; 1.0158x over previous
#include <cuda_runtime.h>
#include <cuda_fp16.h>
#include <math.h>
#include <stdint.h>

#define BATCH 32768
#define FDIM 512
#define HS 256
#define OUTD 128
#define STEPS 5
#define EPSBN 1e-5f

typedef __half fp16;

// ---------------- scratch (device globals; no allocation) ----------------
__device__ fp16  g_featsh[BATCH * FDIM];
__device__ fp16  g_A[BATCH * FDIM];
__device__ fp16  g_h0[BATCH * HS];
__device__ fp16  g_h1[BATCH * HS];
__device__ float g_z[BATCH * FDIM];
__device__ float g_prior[BATCH * FDIM];
__device__ float g_acc[BATCH * OUTD];

// prepped weights ([N,K] fp16; GLU ones N-permuted with 8-col a/b interleave)
__device__ fp16 g_W0[512 * 512];
__device__ fp16 g_W1[512 * 256];
__device__ fp16 g_WU[12 * 512 * 256];
__device__ fp16 g_WA[5 * 512 * 128];
__device__ float g_fts[6 * 4 * 512], g_ftt[6 * 4 * 512];
__device__ float g_as[5 * 512], g_at[5 * 512];

// ---------------- PTX helpers ----------------
__device__ __forceinline__ uint32_t smem_u32(const void* p) {
    uint32_t a;
    asm("{ .reg .u64 t; cvta.to.shared.u64 t, %1; cvt.u32.u64 %0, t; }" : "=r"(a) : "l"(p));
    return a;
}
__device__ __forceinline__ void cpa16(uint32_t s, const void* g) {
    asm volatile("cp.async.cg.shared.global [%0], [%1], 16;" :: "r"(s), "l"(g));
}
__device__ __forceinline__ void cpa_commit() {
    asm volatile("cp.async.commit_group;" ::: "memory");
}
template<int N>
__device__ __forceinline__ void cpa_wait() {
    asm volatile("cp.async.wait_group %0;" :: "n"(N) : "memory");
}
__device__ __forceinline__ void ldm4(uint32_t* v, uint32_t addr) {
    asm volatile("ldmatrix.sync.aligned.m8n8.x4.shared.b16 {%0,%1,%2,%3}, [%4];"
                 : "=r"(v[0]), "=r"(v[1]), "=r"(v[2]), "=r"(v[3]) : "r"(addr));
}
__device__ __forceinline__ void mma16(float* c, const uint32_t* a, uint32_t b0, uint32_t b1) {
    asm("mma.sync.aligned.m16n8k16.row.col.f32.f16.f16.f32 "
        "{%0,%1,%2,%3}, {%4,%5,%6,%7}, {%8,%9}, {%0,%1,%2,%3};"
        : "+f"(c[0]), "+f"(c[1]), "+f"(c[2]), "+f"(c[3])
        : "r"(a[0]), "r"(a[1]), "r"(a[2]), "r"(a[3]), "r"(b0), "r"(b1));
}

// ---------------- prep ----------------
__device__ __forceinline__ void prep_one(const float* W, int K, int idx, fp16* o)
{
    int n = idx / K, k = idx - n * K;
    int q = n >> 4, rr = n & 15, half = rr >> 3, jl = rr & 7;
    int col = (half ? 256 : 0) + q * 8 + jl;
    o[idx] = __float2half_rn(W[(size_t)k * 512 + col]);
}

__global__ void k_prep_glu_all(const float* __restrict__ Ws0,
                               const float* __restrict__ Ws1,
                               const float* __restrict__ Wu)
{
    int idx = blockIdx.x * 256 + threadIdx.x;
    const int N0 = 512 * 512;
    const int N1 = N0 + 512 * 256;
    const int N2 = N1 + 12 * 512 * 256;
    if (idx < N0) {
        prep_one(Ws0, 512, idx, g_W0);
    } else if (idx < N1) {
        prep_one(Ws1, 256, idx - N0, g_W1);
    } else if (idx < N2) {
        int r = idx - N1;
        int mi = r / (512 * 256);
        int li = r - mi * (512 * 256);
        prep_one(Wu + (size_t)mi * 256 * 512, 256, li, g_WU + (size_t)mi * 512 * 256);
    }
}

__global__ void k_prep_att_bn(const float* __restrict__ Wa,
                              const float* __restrict__ fg, const float* __restrict__ fb,
                              const float* __restrict__ fm, const float* __restrict__ fv,
                              const float* __restrict__ ag, const float* __restrict__ ab,
                              const float* __restrict__ am, const float* __restrict__ av)
{
    int idx = blockIdx.x * 256 + threadIdx.x;
    if (idx < 5 * 512 * 128) {
        int s = idx / (512 * 128);
        int r = idx - s * 512 * 128;
        int n = r >> 7, k = r & 127;
        g_WA[idx] = __float2half_rn(Wa[(size_t)s * 128 * 512 + (size_t)k * 512 + n]);
    }
    if (idx < 6 * 4 * 512) {
        float s = fg[idx] * rsqrtf(fv[idx] + EPSBN);
        g_fts[idx] = s;
        g_ftt[idx] = fb[idx] - fm[idx] * s;
    }
    if (idx < 5 * 512) {
        float s = ag[idx] * rsqrtf(av[idx] + EPSBN);
        g_as[idx] = s;
        g_at[idx] = ab[idx] - am[idx] * s;
    }
}

__global__ void k_init(const float* __restrict__ feat,
                       const float* __restrict__ g, const float* __restrict__ b,
                       const float* __restrict__ m, const float* __restrict__ v)
{
    int i = blockIdx.x * blockDim.x + threadIdx.x;
    if (i < BATCH * FDIM) {
        int c = i & (FDIM - 1);
        float f = g[c] * (feat[i] - m[c]) * rsqrtf(v[c] + EPSBN) + b[c];
        fp16 h = __float2half_rn(f);
        g_featsh[i] = h;
        g_A[i] = h;
        g_prior[i] = 1.0f;
        if (i < BATCH * OUTD) g_acc[i] = 0.0f;
    }
}

// ---------------- HMMA GEMM: MODE 0 = GLU, MODE 1 = attention ----------------
// 256 threads, 3 CTAs/SM. BM=64, BN=128, BK=64. Warp grid 2(M)x4(N), warp tile 32x32.
// 3-stage cp.async ring, ONE barrier per chunk.
#define STAGE_BYTES 24576     // A 8K | B 16K
#define NSTAGE 3
#define PARAM_OFF   (NSTAGE * STAGE_BYTES)
#define SMEM_TOTAL  (PARAM_OFF + 1024)

template<int MODE>
__global__ __launch_bounds__(256, 3)
void k_mma(const fp16* __restrict__ A, int lda, int K,
           const fp16* __restrict__ B,
           const float* __restrict__ bs, const float* __restrict__ bt,
           const fp16* __restrict__ resh,
           fp16* __restrict__ outh,
           float* __restrict__ accp,
           const float* __restrict__ prior, float* __restrict__ zout)
{
    extern __shared__ __align__(128) char smem[];
    const int tid = threadIdx.x, wid = tid >> 5, lid = tid & 31;
    const int wm = wid >> 2, wn = wid & 3;
    const int g = blockIdx.x;
    const int row0 = blockIdx.y * 64;
    const uint32_t sb = smem_u32(smem);

    // stage fused-BN params (128 prepped per CTA)
    if (tid < 128) {
        float* sE = (float*)(smem + PARAM_OFF);
        float* tE = (float*)(smem + PARAM_OFF + 512);
        int col;
        if (MODE == 0) {
            int q2 = tid >> 4, rr = tid & 15, half = rr >> 3, jl = rr & 7;
            col = (half ? 256 : 0) + g * 64 + q2 * 8 + jl;
        } else {
            col = g * 128 + tid;
        }
        sE[tid] = bs[col];
        tE[tid] = bt[col];
    }

    float acc[8][4];
#pragma unroll
    for (int i = 0; i < 8; i++)
#pragma unroll
        for (int j = 0; j < 4; j++) acc[i][j] = 0.0f;

    const int nch = K >> 6;

    // per-thread load indices: A 2 pieces (64 rows), B 4 pieces (128 rows)
    const char* gA[2];
    const char* gB[4];
    uint32_t soA[2], soB[4];
#pragma unroll
    for (int i = 0; i < 2; i++) {
        int idx = tid + i * 256;
        int r = idx >> 3, c = idx & 7;
        soA[i] = (uint32_t)(r * 128 + ((c ^ (r & 7)) << 4));
        gA[i] = (const char*)(A + (size_t)(row0 + r) * lda + c * 8);
    }
#pragma unroll
    for (int i = 0; i < 4; i++) {
        int idx = tid + i * 256;
        int r = idx >> 3, c = idx & 7;
        soB[i] = (uint32_t)(8192 + r * 128 + ((c ^ (r & 7)) << 4));
        gB[i] = (const char*)(B + (size_t)(g * 128 + r) * K + c * 8);
    }

    auto load_stage = [&](int ch) {
        const uint32_t st = sb + (ch % NSTAGE) * STAGE_BYTES;
        const int kb = ch << 7;
#pragma unroll
        for (int i = 0; i < 2; i++) cpa16(st + soA[i], gA[i] + kb);
#pragma unroll
        for (int i = 0; i < 4; i++) cpa16(st + soB[i], gB[i] + kb);
    };

    // prologue: 2 groups
#pragma unroll
    for (int p = 0; p < 2; p++) {
        if (p < nch) load_stage(p);
        cpa_commit();
    }

    const int lr = lid & 15, lc = lid >> 4;
    uint32_t offA[2], offB2[2];
#pragma unroll
    for (int m = 0; m < 2; m++) {
        int r = wm * 32 + m * 16 + lr;
        offA[m] = (uint32_t)(r * 128 + ((lc ^ (r & 7)) << 4));
    }
#pragma unroll
    for (int q = 0; q < 2; q++) {
        int r = wn * 32 + q * 16 + lr;
        offB2[q] = (uint32_t)(8192 + r * 128 + ((lc ^ (r & 7)) << 4));
    }

    for (int ch = 0; ch < nch; ch++) {
        cpa_wait<1>();
        __syncthreads();   // stage ch visible; all warps done with chunk ch-1
        if (ch + 2 < nch) load_stage(ch + 2);
        cpa_commit();

        const uint32_t st = sb + (ch % NSTAGE) * STAGE_BYTES;
        uint32_t aH0 = st + offA[0], aH1 = st + offA[1];
        uint32_t aB0 = st + offB2[0], aB1 = st + offB2[1];

#pragma unroll
        for (int ks = 0; ks < 4; ks++) {
            uint32_t ah[2][4], bq[2][4];
            ldm4(ah[0], aH0); ldm4(ah[1], aH1);
            ldm4(bq[0], aB0); ldm4(bq[1], aB1);
#pragma unroll
            for (int m = 0; m < 2; m++) {
                mma16(acc[m * 4 + 0], ah[m], bq[0][0], bq[0][2]);
                mma16(acc[m * 4 + 1], ah[m], bq[0][1], bq[0][3]);
                mma16(acc[m * 4 + 2], ah[m], bq[1][0], bq[1][2]);
                mma16(acc[m * 4 + 3], ah[m], bq[1][1], bq[1][3]);
            }
            const uint32_t d = (ks & 1) ? 96u : 32u;
            aH0 ^= d; aH1 ^= d;
            aB0 ^= d; aB1 ^= d;
        }
        // no trailing barrier: next chunk's post-wait barrier protects the ring
    }
    // no pre-epilogue barrier: epilogue reads only regs + pre-loop smem params

    // ---------------- epilogue ----------------
    const float* sE = (const float*)(smem + PARAM_OFF);
    const float* tE = (const float*)(smem + PARAM_OFF + 512);
    const int gid = lid >> 2, tp = lid & 3;

    if (MODE == 0) {
#pragma unroll
        for (int m = 0; m < 2; m++) {
#pragma unroll
            for (int t = 0; t < 2; t++) {
                const int ja = wn * 32 + t * 16 + tp * 2;   // prepped local a idx
                const int jb = ja + 8;                      // paired b idx
                const int cn = g * 64 + (wn * 2 + t) * 8 + tp * 2;  // output col
                const float sa0 = sE[ja], sa1 = sE[ja + 1];
                const float ta0 = tE[ja], ta1 = tE[ja + 1];
                const float sb0 = sE[jb], sb1 = sE[jb + 1];
                const float tb0 = tE[jb], tb1 = tE[jb + 1];
                const float* ca = acc[m * 4 + 2 * t];
                const float* cb = acc[m * 4 + 2 * t + 1];
#pragma unroll
                for (int h = 0; h < 2; h++) {
                    const int row = row0 + wm * 32 + m * 16 + gid + h * 8;
                    float xa0 = ca[2 * h] * sa0 + ta0;
                    float xa1 = ca[2 * h + 1] * sa1 + ta1;
                    float xb0 = cb[2 * h] * sb0 + tb0;
                    float xb1 = cb[2 * h + 1] * sb1 + tb1;
                    float o0 = xa0 * (1.0f / (1.0f + __expf(-xb0)));
                    float o1 = xa1 * (1.0f / (1.0f + __expf(-xb1)));
                    const size_t ob = (size_t)row * HS + cn;
                    if (resh) {
                        __half2 rh = *(const __half2*)(resh + ob);
                        o0 = fmaf(__half2float(rh.x), 0.70710678118654752f, o0);
                        o1 = fmaf(__half2float(rh.y), 0.70710678118654752f, o1);
                    }
                    __half2 hh;
                    hh.x = __float2half_rn(o0);
                    hh.y = __float2half_rn(o1);
                    *(__half2*)(outh + ob) = hh;
                    if (accp && g < 2) {
                        float2* ap = (float2*)(accp + (size_t)row * OUTD + cn);
                        float2 av = *ap;
                        av.x += fmaxf(o0, 0.0f);
                        av.y += fmaxf(o1, 0.0f);
                        *ap = av;
                    }
                }
            }
        }
    } else {
#pragma unroll
        for (int m = 0; m < 2; m++) {
#pragma unroll
            for (int nb = 0; nb < 4; nb++) {
                const int cn = wn * 32 + nb * 8 + tp * 2;
                const float s0 = sE[cn], s1 = sE[cn + 1];
                const float t0 = tE[cn], t1 = tE[cn + 1];
                const float* ca = acc[m * 4 + nb];
#pragma unroll
                for (int h = 0; h < 2; h++) {
                    const int row = row0 + wm * 32 + m * 16 + gid + h * 8;
                    const size_t idx = (size_t)row * FDIM + g * 128 + cn;
                    float2 pr = *(const float2*)(prior + idx);
                    float2 zz;
                    zz.x = (ca[2 * h] * s0 + t0) * pr.x;
                    zz.y = (ca[2 * h + 1] * s1 + t1) * pr.y;
                    *(float2*)(zout + idx) = zz;
                }
            }
        }
    }
}

// ---------------- sparsemax: one warp per row ----------------
__global__ __launch_bounds__(256)
void k_sparsemax(const float* __restrict__ z, float* __restrict__ prior,
                 float* __restrict__ maskOut, fp16* __restrict__ mf)
{
    const int row = blockIdx.x * 8 + (threadIdx.x >> 5);
    const int lid = threadIdx.x & 31;
    const size_t base = (size_t)row * 512;
    float v[16];
#pragma unroll
    for (int q = 0; q < 4; q++) {
        float4 t = *(const float4*)(z + base + q * 128 + lid * 4);
        v[q * 4 + 0] = t.x; v[q * 4 + 1] = t.y; v[q * 4 + 2] = t.z; v[q * 4 + 3] = t.w;
    }
    float zmax = v[0];
#pragma unroll
    for (int i = 1; i < 16; i++) zmax = fmaxf(zmax, v[i]);
#pragma unroll
    for (int o = 16; o; o >>= 1) zmax = fmaxf(zmax, __shfl_xor_sync(0xffffffffu, zmax, o));

    float lo = zmax - 1.0f, hi = zmax;
    for (int it = 0; it < 20; it++) {
        float mid = 0.5f * (lo + hi);
        float s = 0.0f;
#pragma unroll
        for (int i = 0; i < 16; i++) s += fmaxf(v[i] - mid, 0.0f);
#pragma unroll
        for (int o = 16; o; o >>= 1) s += __shfl_xor_sync(0xffffffffu, s, o);
        if (s >= 1.0f) lo = mid; else hi = mid;
    }
    float sum = 0.0f, cnt = 0.0f;
#pragma unroll
    for (int i = 0; i < 16; i++) {
        if (v[i] > lo) { sum += v[i]; cnt += 1.0f; }
    }
#pragma unroll
    for (int o = 16; o; o >>= 1) {
        sum += __shfl_xor_sync(0xffffffffu, sum, o);
        cnt += __shfl_xor_sync(0xffffffffu, cnt, o);
    }
    const float tau = (sum - 1.0f) / cnt;

#pragma unroll
    for (int q = 0; q < 4; q++) {
        const size_t off = base + q * 128 + lid * 4;
        float4 mk;
        mk.x = fmaxf(v[q * 4 + 0] - tau, 0.0f);
        mk.y = fmaxf(v[q * 4 + 1] - tau, 0.0f);
        mk.z = fmaxf(v[q * 4 + 2] - tau, 0.0f);
        mk.w = fmaxf(v[q * 4 + 3] - tau, 0.0f);
        *(float4*)(maskOut + off) = mk;
        float4 pr = *(const float4*)(prior + off);
        pr.x *= (1.5f - mk.x); pr.y *= (1.5f - mk.y);
        pr.z *= (1.5f - mk.z); pr.w *= (1.5f - mk.w);
        *(float4*)(prior + off) = pr;
        __half2 f01 = *(const __half2*)(g_featsh + off);
        __half2 f23 = *(const __half2*)(g_featsh + off + 2);
        __half2 p0, p1;
        p0.x = __float2half_rn(mk.x * __half2float(f01.x));
        p0.y = __float2half_rn(mk.y * __half2float(f01.y));
        p1.x = __float2half_rn(mk.z * __half2float(f23.x));
        p1.y = __float2half_rn(mk.w * __half2float(f23.y));
        *(__half2*)(mf + off) = p0;
        *(__half2*)(mf + off + 2) = p1;
    }
}

// ---------------- final projection ----------------
__global__ __launch_bounds__(256)
void k_fin(const float* __restrict__ A, const float* __restrict__ W,
           const float* __restrict__ bias, float* __restrict__ C)
{
    __shared__ float As[16][128];
    __shared__ float Ws[16][64];
    const int tid = threadIdx.x;
    const int ty = tid >> 4, tx = tid & 15;
    const int row0 = blockIdx.y * 128;
    const int col0 = blockIdx.x * 64;

    float acc[8][4];
#pragma unroll
    for (int r = 0; r < 8; r++)
#pragma unroll
        for (int c = 0; c < 4; c++) acc[r][c] = 0.f;

    for (int kt = 0; kt < 128; kt += 16) {
#pragma unroll
        for (int l = 0; l < 2; l++) {
            int li = tid * 2 + l;
            int r = li >> 2, kq = (li & 3) * 4;
            float4 av = *(const float4*)(A + (size_t)(row0 + r) * 128 + kt + kq);
            As[kq + 0][r] = av.x; As[kq + 1][r] = av.y;
            As[kq + 2][r] = av.z; As[kq + 3][r] = av.w;
        }
        *(float4*)&Ws[tid >> 4][(tid & 15) * 4] =
            *(const float4*)(W + (size_t)(kt + (tid >> 4)) * 128 + col0 + (tid & 15) * 4);
        __syncthreads();
#pragma unroll
        for (int kk = 0; kk < 16; kk++) {
            float a[8];
            float4 a0 = *(float4*)&As[kk][ty * 8];
            float4 a1 = *(float4*)&As[kk][ty * 8 + 4];
            a[0] = a0.x; a[1] = a0.y; a[2] = a0.z; a[3] = a0.w;
            a[4] = a1.x; a[5] = a1.y; a[6] = a1.z; a[7] = a1.w;
            float4 w0 = *(float4*)&Ws[kk][tx * 4];
            float wv[4] = {w0.x, w0.y, w0.z, w0.w};
#pragma unroll
            for (int r = 0; r < 8; r++)
#pragma unroll
                for (int c = 0; c < 4; c++) acc[r][c] += a[r] * wv[c];
        }
        __syncthreads();
    }
#pragma unroll
    for (int r = 0; r < 8; r++) {
        int gr = row0 + ty * 8 + r;
#pragma unroll
        for (int c = 0; c < 4; c++) {
            int gc = col0 + tx * 4 + c;
            C[(size_t)gr * 128 + gc] = acc[r][c] + bias[gc];
        }
    }
}

// ---------------- launch ----------------
extern "C" void kernel_launch(void* const* d_in, const int* in_sizes, int n_in,
                              void* d_out, int out_size)
{
    const float* features = (const float*)d_in[0];
    const float* bn0_g = (const float*)d_in[1];
    const float* bn0_b = (const float*)d_in[2];
    const float* bn0_m = (const float*)d_in[3];
    const float* bn0_v = (const float*)d_in[4];
    const float* Ws0   = (const float*)d_in[5];
    const float* Ws1   = (const float*)d_in[6];
    const float* Wu    = (const float*)d_in[7];
    const float* ft_g  = (const float*)d_in[8];
    const float* ft_b  = (const float*)d_in[9];
    const float* ft_m  = (const float*)d_in[10];
    const float* ft_v  = (const float*)d_in[11];
    const float* W_att = (const float*)d_in[12];
    const float* att_g = (const float*)d_in[13];
    const float* att_b = (const float*)d_in[14];
    const float* att_m = (const float*)d_in[15];
    const float* att_v = (const float*)d_in[16];
    const float* Wf    = (const float*)d_in[17];
    const float* bf    = (const float*)d_in[18];

    float *zp, *prior, *acc;
    fp16 *A, *h0, *h1;
    fp16 *W0, *W1, *WU, *WA;
    float *fts, *ftt, *as, *at;
    cudaGetSymbolAddress((void**)&A, g_A);
    cudaGetSymbolAddress((void**)&h0, g_h0);
    cudaGetSymbolAddress((void**)&h1, g_h1);
    cudaGetSymbolAddress((void**)&zp, g_z);
    cudaGetSymbolAddress((void**)&prior, g_prior);
    cudaGetSymbolAddress((void**)&acc, g_acc);
    cudaGetSymbolAddress((void**)&W0, g_W0);
    cudaGetSymbolAddress((void**)&W1, g_W1);
    cudaGetSymbolAddress((void**)&WU, g_WU);
    cudaGetSymbolAddress((void**)&WA, g_WA);
    cudaGetSymbolAddress((void**)&fts, g_fts);
    cudaGetSymbolAddress((void**)&ftt, g_ftt);
    cudaGetSymbolAddress((void**)&as, g_as);
    cudaGetSymbolAddress((void**)&at, g_at);

    float* outF  = (float*)d_out;
    float* masks = outF + (size_t)BATCH * OUTD;

    static bool attr_set = false;
    if (!attr_set) {
        cudaFuncSetAttribute(k_mma<0>, cudaFuncAttributeMaxDynamicSharedMemorySize, SMEM_TOTAL);
        cudaFuncSetAttribute(k_mma<1>, cudaFuncAttributeMaxDynamicSharedMemorySize, SMEM_TOTAL);
        attr_set = true;
    }

    const int PREP_N = 512 * 512 + 512 * 256 + 12 * 512 * 256;
    k_prep_glu_all<<<(PREP_N + 255) / 256, 256>>>(Ws0, Ws1, Wu);
    k_prep_att_bn<<<(5 * 512 * 128 + 255) / 256, 256>>>(W_att, ft_g, ft_b, ft_m, ft_v,
                                                        att_g, att_b, att_m, att_v);
    k_init<<<(BATCH * FDIM) / 256, 256>>>(features, bn0_g, bn0_b, bn0_m, bn0_v);

    const dim3 gMma(4, BATCH / 64);

    auto ft_transformer = [&](int t, float* accOut) {
        const float* s0 = fts + (size_t)t * 4 * 512;
        const float* t0 = ftt + (size_t)t * 4 * 512;
        k_mma<0><<<gMma, 256, SMEM_TOTAL>>>(A, 512, 512, W0,
            s0, t0, nullptr, h0, nullptr, nullptr, nullptr);
        k_mma<0><<<gMma, 256, SMEM_TOTAL>>>(h0, 256, 256, W1,
            s0 + 512, t0 + 512, h0, h1, nullptr, nullptr, nullptr);
        k_mma<0><<<gMma, 256, SMEM_TOTAL>>>(h1, 256, 256,
            WU + (size_t)(t * 2 + 0) * 512 * 256,
            s0 + 1024, t0 + 1024, h1, h0, nullptr, nullptr, nullptr);
        k_mma<0><<<gMma, 256, SMEM_TOTAL>>>(h0, 256, 256,
            WU + (size_t)(t * 2 + 1) * 512 * 256,
            s0 + 1536, t0 + 1536, h0, h1, accOut, nullptr, nullptr);
    };

    ft_transformer(0, nullptr);

    for (int s = 0; s < STEPS; s++) {
        k_mma<1><<<gMma, 256, SMEM_TOTAL>>>(h1 + 128, 256, 128,
            WA + (size_t)s * 512 * 128,
            as + (size_t)s * 512, at + (size_t)s * 512,
            nullptr, nullptr, nullptr,
            prior, zp);
        k_sparsemax<<<BATCH / 8, 256>>>(zp, prior, masks + (size_t)s * BATCH * FDIM, A);
        ft_transformer(s + 1, acc);
    }

    k_fin<<<dim3(2, BATCH / 128), 256>>>(acc, Wf, bf, outF);
}